// round 5
// baseline (speedup 1.0000x reference)
#include <cuda_runtime.h>

// Depthwise 3x3 (center tap zero) + residual, NHWC x[32,56,56,256] fp32.
// R3 (37.6us, DRAM 64.5%) was still latency-exposed: batch loads were
// consumed ~20 instructions later. R5 = R3 + explicit prefetch: next batch's
// 12 loads issue BEFORE the current batch's 64 FMAs + 4 stores (load->use
// distance ~80 instr), merged into the window at batch end. Streaming
// stores (__stcs) keep input rows resident in L2 (tensor ~fits in 126MB L2).

#define Bn 32
#define Hn 56
#define Wn 56
#define C2 128   // 256 channels / 2 per float2

__device__ __forceinline__ float2 f2fma(float2 k, float2 v, float2 a) {
    a.x = fmaf(k.x, v.x, a.x);
    a.y = fmaf(k.y, v.y, a.y);
    return a;
}

__global__ __launch_bounds__(256, 2)
void contour_integration_kernel(const float2* __restrict__ x,
                                const float2* __restrict__ k,
                                float2* __restrict__ out)
{
    const int c2 = threadIdx.x;                    // 0..127 channel pair
    const int bh = blockIdx.x * 2 + threadIdx.y;   // 0..B*H-1
    const int h  = bh % Hn;

    const float2 Z = make_float2(0.f, 0.f);

    // taps (cross-correlation; center k[1][1] excluded)
    float2 k00 = __ldg(&k[0 * C2 + c2]);
    float2 k01 = __ldg(&k[1 * C2 + c2]);
    float2 k02 = __ldg(&k[2 * C2 + c2]);
    float2 k10 = __ldg(&k[3 * C2 + c2]);
    float2 k12 = __ldg(&k[5 * C2 + c2]);
    float2 k20 = __ldg(&k[6 * C2 + c2]);
    float2 k21 = __ldg(&k[7 * C2 + c2]);
    float2 k22 = __ldg(&k[8 * C2 + c2]);

    // boundary rows: zero taps + clamp pointer -> all row loads unconditional
    const bool hm = (h > 0);
    const bool hp = (h < Hn - 1);
    if (!hm) { k00 = Z; k01 = Z; k02 = Z; }
    if (!hp) { k20 = Z; k21 = Z; k22 = Z; }

    const int base = bh * Wn * C2 + c2;            // 32-bit safe
    const float2* __restrict__ row1 = x + base;
    const float2* __restrict__ row0 = hm ? (row1 - Wn * C2) : row1;
    const float2* __restrict__ row2 = hp ? (row1 + Wn * C2) : row1;
    float2* __restrict__ orow = out + base;

    // window: win[row][p], p=0..5 = columns w-1 .. w+4 for batch start w
    float2 win[3][6];

    win[0][0] = Z; win[1][0] = Z; win[2][0] = Z;   // col -1
    #pragma unroll
    for (int p = 1; p <= 5; ++p) {
        const int wc = p - 1;
        win[0][p] = __ldg(&row0[wc * C2]);
        win[1][p] = __ldg(&row1[wc * C2]);
        win[2][p] = __ldg(&row2[wc * C2]);
    }

    #pragma unroll
    for (int bidx = 0; bidx < 14; ++bidx) {
        const int w = bidx * 4;

        // ---- prefetch next batch (cols w+5..w+8) FIRST: max load->use gap
        float2 nxt[3][4];
        if (bidx < 13) {
            #pragma unroll
            for (int j = 0; j < 4; ++j) {
                const int wc = w + 5 + j;          // compile-time constant
                if (wc < Wn) {
                    nxt[0][j] = __ldg(&row0[wc * C2]);
                    nxt[1][j] = __ldg(&row1[wc * C2]);
                    nxt[2][j] = __ldg(&row2[wc * C2]);
                } else {
                    nxt[0][j] = Z; nxt[1][j] = Z; nxt[2][j] = Z;
                }
            }
        }

        // ---- compute 4 outputs w..w+3 from the (already resident) window
        #pragma unroll
        for (int j = 0; j < 4; ++j) {
            float2 acc = win[1][j + 1];            // residual (center x)
            acc = f2fma(k00, win[0][j],     acc);
            acc = f2fma(k01, win[0][j + 1], acc);
            acc = f2fma(k02, win[0][j + 2], acc);
            acc = f2fma(k10, win[1][j],     acc);
            acc = f2fma(k12, win[1][j + 2], acc);
            acc = f2fma(k20, win[2][j],     acc);
            acc = f2fma(k21, win[2][j + 1], acc);
            acc = f2fma(k22, win[2][j + 2], acc);
            __stcs(&orow[(w + j) * C2], acc);      // streaming store
        }

        // ---- merge prefetched data into the window
        if (bidx < 13) {
            #pragma unroll
            for (int r = 0; r < 3; ++r) {
                win[r][0] = win[r][4];
                win[r][1] = win[r][5];
                win[r][2] = nxt[r][0];
                win[r][3] = nxt[r][1];
                win[r][4] = nxt[r][2];
                win[r][5] = nxt[r][3];
            }
        }
    }
}

extern "C" void kernel_launch(void* const* d_in, const int* in_sizes, int n_in,
                              void* d_out, int out_size)
{
    const float2* x = (const float2*)d_in[0];   // [32,56,56,256] fp32
    const float2* k = (const float2*)d_in[1];   // [3,3,256] fp32
    float2* out = (float2*)d_out;

    dim3 block(C2, 2);          // 256 threads: two full rows per block
    dim3 grid(Bn * Hn / 2);     // 896 blocks
    contour_integration_kernel<<<grid, block>>>(x, k, out);
}